// round 1
// baseline (speedup 1.0000x reference)
#include <cuda_runtime.h>
#include <math.h>

// Problem dims
constexpr int BB = 8;
constexpr int SS = 1024;
constexpr int DD = 256;
constexpr int MTOT = BB * SS;          // 8192

// Scratch (device globals — no cudaMalloc allowed)
__device__ float g_q[MTOT * DD];
__device__ float g_k[MTOT * DD];
__device__ float g_f[MTOT * DD];
__device__ float g_i[MTOT * DD];
__device__ float g_n[MTOT * DD];
__device__ float g_h[MTOT * DD];
__device__ float g_inv[MTOT];

// ---------------------------------------------------------------------------
// GEMM: out[m,n] = act( sum_k A[m,k] * W[n,k] + bias[n] )
// A: [M=8192, K=256] row-major, W: [N=256, K=256] row-major (torch Linear).
// BM=BN=64, BK=16, 256 threads, 4x4 per thread.
// ACT: 0 = none, 1 = sigmoid, 2 = exp
// ---------------------------------------------------------------------------
template <int ACT>
__global__ void __launch_bounds__(256) gemm_kernel(
    const float* __restrict__ A, const float* __restrict__ W,
    const float* __restrict__ bias, float* __restrict__ out)
{
    constexpr int K = DD, N = DD;
    __shared__ float As[16][68];
    __shared__ float Bs[16][68];

    const int tid = threadIdx.x;
    const int m0 = blockIdx.y * 64;
    const int n0 = blockIdx.x * 64;
    const int lm = tid >> 2;            // 0..63
    const int lk = (tid & 3) << 2;      // 0,4,8,12
    const int tx = tid & 15;
    const int ty = tid >> 4;

    float acc[4][4] = {};

    for (int k0 = 0; k0 < K; k0 += 16) {
        float4 a4 = *(const float4*)(A + (size_t)(m0 + lm) * K + k0 + lk);
        float4 w4 = *(const float4*)(W + (size_t)(n0 + lm) * K + k0 + lk);
        As[lk + 0][lm] = a4.x; As[lk + 1][lm] = a4.y;
        As[lk + 2][lm] = a4.z; As[lk + 3][lm] = a4.w;
        Bs[lk + 0][lm] = w4.x; Bs[lk + 1][lm] = w4.y;
        Bs[lk + 2][lm] = w4.z; Bs[lk + 3][lm] = w4.w;
        __syncthreads();
#pragma unroll
        for (int kk = 0; kk < 16; kk++) {
            float4 av = *(const float4*)&As[kk][ty * 4];
            float4 bv = *(const float4*)&Bs[kk][tx * 4];
            float ar[4] = {av.x, av.y, av.z, av.w};
            float br[4] = {bv.x, bv.y, bv.z, bv.w};
#pragma unroll
            for (int i2 = 0; i2 < 4; i2++)
#pragma unroll
                for (int j2 = 0; j2 < 4; j2++)
                    acc[i2][j2] = fmaf(ar[i2], br[j2], acc[i2][j2]);
        }
        __syncthreads();
    }

    float4 b4 = *(const float4*)(bias + n0 + tx * 4);
    float bb[4] = {b4.x, b4.y, b4.z, b4.w};
#pragma unroll
    for (int i2 = 0; i2 < 4; i2++) {
        float4 o;
        float* op = &o.x;
#pragma unroll
        for (int j2 = 0; j2 < 4; j2++) {
            float v = acc[i2][j2] + bb[j2];
            if (ACT == 1) v = 1.0f / (1.0f + expf(-v));
            else if (ACT == 2) v = expf(v);
            op[j2] = v;
        }
        *(float4*)(out + (size_t)(m0 + ty * 4 + i2) * N + n0 + tx * 4) = o;
    }
}

// ---------------------------------------------------------------------------
// n-scan: n_t[j] = f_t[j]*n_{t-1}[j] + i_t[j]*k_t[j]  (per (b,j) independent)
// grid 16 blocks x 128 threads: 2048 channel-chains.
// ---------------------------------------------------------------------------
__global__ void nscan_kernel()
{
    const int b = blockIdx.x >> 1;
    const int j = ((blockIdx.x & 1) << 7) + threadIdx.x;
    const size_t base = (size_t)b * SS * DD + j;
    float n = 0.0f;
#pragma unroll 8
    for (int t = 0; t < SS; t++) {
        size_t o = base + (size_t)t * DD;
        n = fmaf(g_f[o], n, g_i[o] * g_k[o]);
        g_n[o] = n;
    }
}

// ---------------------------------------------------------------------------
// den: inv_den[b,t] = 1 / max(|n_t . q_t|, 1).  One warp per (b,t).
// ---------------------------------------------------------------------------
__global__ void den_kernel()
{
    const int warp = threadIdx.x >> 5;
    const int lane = threadIdx.x & 31;
    const int m = blockIdx.x * 8 + warp;      // m in [0, 8192)
    const size_t base = (size_t)m * DD + lane * 8;
    float4 na = *(const float4*)(g_n + base);
    float4 nb = *(const float4*)(g_n + base + 4);
    float4 qa = *(const float4*)(g_q + base);
    float4 qb = *(const float4*)(g_q + base + 4);
    float d = na.x * qa.x + na.y * qa.y + na.z * qa.z + na.w * qa.w
            + nb.x * qb.x + nb.y * qb.y + nb.z * qb.z + nb.w * qb.w;
#pragma unroll
    for (int o = 16; o; o >>= 1) d += __shfl_xor_sync(0xffffffffu, d, o);
    if (lane == 0) g_inv[m] = 1.0f / fmaxf(fabsf(d), 1.0f);
}

// ---------------------------------------------------------------------------
// C-scan: one warp per (batch, row). Lane owns 8 contiguous columns of C
// in registers. Per step:
//   C[r,c] = f_t[r]*C[r,c] + (i_t[r]*v_t[r])*k_t[c];  num = C[r,:].q_t
//   h[b,t,r] = num * inv_den[b,t]      (v == q by reference definition)
// Software-pipelined global loads, prefetch depth 2.
// grid = 8 batches * 16 CTAs, 512 threads (16 warps = 16 rows per CTA).
// ---------------------------------------------------------------------------
__global__ void __launch_bounds__(512, 1) cscan_kernel()
{
    const int b = blockIdx.x >> 4;
    const int r0 = (blockIdx.x & 15) << 4;
    const int warp = threadIdx.x >> 5;
    const int lane = threadIdx.x & 31;
    const int row = r0 + warp;
    const size_t mb = (size_t)b * SS * DD;

    const float* pk = g_k + mb + lane * 8;
    const float* pq = g_q + mb + lane * 8;
    const float* pf = g_f + mb + row;
    const float* pi = g_i + mb + row;
    const float* pv = g_q + mb + row;   // v == q
    const float* pd = g_inv + b * SS;
    float* ph = g_h + mb + row;

    float C[8] = {0, 0, 0, 0, 0, 0, 0, 0};

    float4 ka[2], kb[2], qa[2], qb[2];
    float fs[2], is[2], vs[2], ds[2];
#pragma unroll
    for (int p = 0; p < 2; p++) {
        size_t o = (size_t)p * DD;
        ka[p] = *(const float4*)(pk + o); kb[p] = *(const float4*)(pk + o + 4);
        qa[p] = *(const float4*)(pq + o); qb[p] = *(const float4*)(pq + o + 4);
        fs[p] = pf[o]; is[p] = pi[o]; vs[p] = pv[o]; ds[p] = pd[p];
    }

    for (int t = 0; t < SS; t++) {
        const int s = t & 1;
        const float f = fs[s];
        const float a = is[s] * vs[s];
        const float dinv = ds[s];
        const float4 K0 = ka[s], K1 = kb[s], Q0 = qa[s], Q1 = qb[s];

        // prefetch t+2 into the slot we just consumed
        if (t + 2 < SS) {
            size_t o = (size_t)(t + 2) * DD;
            ka[s] = *(const float4*)(pk + o); kb[s] = *(const float4*)(pk + o + 4);
            qa[s] = *(const float4*)(pq + o); qb[s] = *(const float4*)(pq + o + 4);
            fs[s] = pf[o]; is[s] = pi[o]; vs[s] = pv[o]; ds[s] = pd[t + 2];
        }

        C[0] = fmaf(f, C[0], a * K0.x); C[1] = fmaf(f, C[1], a * K0.y);
        C[2] = fmaf(f, C[2], a * K0.z); C[3] = fmaf(f, C[3], a * K0.w);
        C[4] = fmaf(f, C[4], a * K1.x); C[5] = fmaf(f, C[5], a * K1.y);
        C[6] = fmaf(f, C[6], a * K1.z); C[7] = fmaf(f, C[7], a * K1.w);

        float d0 = C[0] * Q0.x, d1 = C[1] * Q0.y;
        float d2 = C[2] * Q0.z, d3 = C[3] * Q0.w;
        d0 = fmaf(C[4], Q1.x, d0); d1 = fmaf(C[5], Q1.y, d1);
        d2 = fmaf(C[6], Q1.z, d2); d3 = fmaf(C[7], Q1.w, d3);
        float num = (d0 + d1) + (d2 + d3);
#pragma unroll
        for (int o2 = 16; o2; o2 >>= 1)
            num += __shfl_xor_sync(0xffffffffu, num, o2);

        if (lane == 0) ph[(size_t)t * DD] = num * dinv;
    }
}

// ---------------------------------------------------------------------------
// Launch
// ---------------------------------------------------------------------------
extern "C" void kernel_launch(void* const* d_in, const int* in_sizes, int n_in,
                              void* d_out, int out_size)
{
    const float* x   = (const float*)d_in[0];
    const float* Wq  = (const float*)d_in[1];
    const float* bq  = (const float*)d_in[2];
    const float* Wk  = (const float*)d_in[3];
    const float* bkk = (const float*)d_in[4];
    // d_in[5] = Wv, d_in[6] = bv — unused (reference uses W_q for v)
    const float* Wf  = (const float*)d_in[7];
    const float* bff = (const float*)d_in[8];
    const float* Wi  = (const float*)d_in[9];
    const float* bii = (const float*)d_in[10];
    const float* Wo  = (const float*)d_in[11];
    const float* bo  = (const float*)d_in[12];
    float* out = (float*)d_out;

    float *pq, *pk, *pf, *pi, *ph;
    cudaGetSymbolAddress((void**)&pq, g_q);
    cudaGetSymbolAddress((void**)&pk, g_k);
    cudaGetSymbolAddress((void**)&pf, g_f);
    cudaGetSymbolAddress((void**)&pi, g_i);
    cudaGetSymbolAddress((void**)&ph, g_h);

    dim3 ggrid(DD / 64, MTOT / 64);   // (4, 128)

    gemm_kernel<0><<<ggrid, 256>>>(x, Wq, bq, pq);
    gemm_kernel<0><<<ggrid, 256>>>(x, Wk, bkk, pk);
    gemm_kernel<1><<<ggrid, 256>>>(x, Wf, bff, pf);
    gemm_kernel<2><<<ggrid, 256>>>(x, Wi, bii, pi);

    nscan_kernel<<<16, 128>>>();
    den_kernel<<<MTOT / 8, 256>>>();
    cscan_kernel<<<BB * 16, 512>>>();

    gemm_kernel<0><<<ggrid, 256>>>(ph, Wo, bo, out);
}

// round 2
// speedup vs baseline: 1.9872x; 1.9872x over previous
#include <cuda_runtime.h>
#include <math.h>

// Problem dims
constexpr int BB = 8;
constexpr int SS = 1024;
constexpr int DD = 256;
constexpr int MTOT = BB * SS;          // 8192
constexpr int PAD = 4 * DD;            // prefetch overrun pad

// Scratch (device globals — no cudaMalloc allowed)
__device__ float g_q[MTOT * DD + PAD];
__device__ float g_k[MTOT * DD + PAD];
__device__ float g_f[MTOT * DD + PAD];
__device__ float g_i[MTOT * DD + PAD];
__device__ float g_n[MTOT * DD];
__device__ float g_h[MTOT * DD];
__device__ float g_inv[MTOT + 16];

// ---------------------------------------------------------------------------
// GEMM: out[m,n] = act( sum_k A[m,k] * W[n,k] + bias[n] )
// A: [8192,256] rm, W: [256,256] rm (torch Linear). 64x64x16 tile, 4x4/thread.
// ACT: 0 none, 1 sigmoid, 2 exp
// ---------------------------------------------------------------------------
template <int ACT>
__global__ void __launch_bounds__(256) gemm_kernel(
    const float* __restrict__ A, const float* __restrict__ W,
    const float* __restrict__ bias, float* __restrict__ out)
{
    constexpr int K = DD, N = DD;
    __shared__ float As[16][68];
    __shared__ float Bs[16][68];

    const int tid = threadIdx.x;
    const int m0 = blockIdx.y * 64;
    const int n0 = blockIdx.x * 64;
    const int lm = tid >> 2;
    const int lk = (tid & 3) << 2;
    const int tx = tid & 15;
    const int ty = tid >> 4;

    float acc[4][4] = {};

    for (int k0 = 0; k0 < K; k0 += 16) {
        float4 a4 = *(const float4*)(A + (size_t)(m0 + lm) * K + k0 + lk);
        float4 w4 = *(const float4*)(W + (size_t)(n0 + lm) * K + k0 + lk);
        As[lk + 0][lm] = a4.x; As[lk + 1][lm] = a4.y;
        As[lk + 2][lm] = a4.z; As[lk + 3][lm] = a4.w;
        Bs[lk + 0][lm] = w4.x; Bs[lk + 1][lm] = w4.y;
        Bs[lk + 2][lm] = w4.z; Bs[lk + 3][lm] = w4.w;
        __syncthreads();
#pragma unroll
        for (int kk = 0; kk < 16; kk++) {
            float4 av = *(const float4*)&As[kk][ty * 4];
            float4 bv = *(const float4*)&Bs[kk][tx * 4];
            float ar[4] = {av.x, av.y, av.z, av.w};
            float br[4] = {bv.x, bv.y, bv.z, bv.w};
#pragma unroll
            for (int i2 = 0; i2 < 4; i2++)
#pragma unroll
                for (int j2 = 0; j2 < 4; j2++)
                    acc[i2][j2] = fmaf(ar[i2], br[j2], acc[i2][j2]);
        }
        __syncthreads();
    }

    float4 b4 = *(const float4*)(bias + n0 + tx * 4);
    float bb[4] = {b4.x, b4.y, b4.z, b4.w};
#pragma unroll
    for (int i2 = 0; i2 < 4; i2++) {
        float4 o;
        float* op = &o.x;
#pragma unroll
        for (int j2 = 0; j2 < 4; j2++) {
            float v = acc[i2][j2] + bb[j2];
            if (ACT == 1) v = 1.0f / (1.0f + expf(-v));
            else if (ACT == 2) v = expf(v);
            op[j2] = v;
        }
        *(float4*)(out + (size_t)(m0 + ty * 4 + i2) * N + n0 + tx * 4) = o;
    }
}

// ---------------------------------------------------------------------------
// n-scan: n_t[j] = f_t[j]*n_{t-1}[j] + i_t[j]*k_t[j]
// ---------------------------------------------------------------------------
__global__ void nscan_kernel()
{
    const int b = blockIdx.x >> 1;
    const int j = ((blockIdx.x & 1) << 7) + threadIdx.x;
    const size_t base = (size_t)b * SS * DD + j;
    float n = 0.0f;
#pragma unroll 8
    for (int t = 0; t < SS; t++) {
        size_t o = base + (size_t)t * DD;
        n = fmaf(g_f[o], n, g_i[o] * g_k[o]);
        g_n[o] = n;
    }
}

// ---------------------------------------------------------------------------
// den: inv_den[b,t] = 1 / max(|n_t . q_t|, 1).  One warp per (b,t).
// ---------------------------------------------------------------------------
__global__ void den_kernel()
{
    const int warp = threadIdx.x >> 5;
    const int lane = threadIdx.x & 31;
    const int m = blockIdx.x * 8 + warp;
    const size_t base = (size_t)m * DD + lane * 8;
    float4 na = *(const float4*)(g_n + base);
    float4 nb = *(const float4*)(g_n + base + 4);
    float4 qa = *(const float4*)(g_q + base);
    float4 qb = *(const float4*)(g_q + base + 4);
    float d = na.x * qa.x + na.y * qa.y + na.z * qa.z + na.w * qa.w
            + nb.x * qb.x + nb.y * qb.y + nb.z * qb.z + nb.w * qb.w;
#pragma unroll
    for (int o = 16; o; o >>= 1) d += __shfl_xor_sync(0xffffffffu, d, o);
    if (lane == 0) g_inv[m] = 1.0f / fmaxf(fabsf(d), 1.0f);
}

// ---------------------------------------------------------------------------
// C-scan, rescaled form. One warp per 2 rows, lane owns 8 columns.
//   g_t[r]   = prod of f within current 16-step chunk  (bounded, renormed)
//   C~_t     = C_chunkstart + sum_s (i_s v_s / g_s) k_s     (1 FFMA/elem)
//   num_t[r] = g_t[r] * (C~_t[r,:] . q_t)
//   h[b,t,r] = num * inv_den[b,t]          (v == q by reference definition)
// Double-buffered prefetch with COMPILE-TIME slot index (16-step unroll) —
// no dynamic register-array indexing, no local-memory spills.
// grid = 8 batches * 16 row-groups = 128 CTAs, 256 threads (8 warps x 2 rows).
// ---------------------------------------------------------------------------
__global__ void __launch_bounds__(256, 1) cscan_kernel()
{
    const int b = blockIdx.x >> 4;
    const int r0 = (blockIdx.x & 15) << 4;
    const int warp = threadIdx.x >> 5;
    const int lane = threadIdx.x & 31;
    const int row0 = r0 + warp * 2;       // and row0+1
    const size_t mb = (size_t)b * SS * DD;

    const float* pk = g_k + mb + lane * 8;
    const float* pq = g_q + mb + lane * 8;
    const float* pf = g_f + mb + row0;
    const float* pi = g_i + mb + row0;
    const float* pv = g_q + mb + row0;    // v == q
    const float* pd = g_inv + b * SS;
    float* ph = g_h + mb + row0;

    float C0[8] = {0,0,0,0,0,0,0,0};
    float C1[8] = {0,0,0,0,0,0,0,0};
    float gg0 = 1.0f, gg1 = 1.0f;

    // double-buffer slots (indexed only by compile-time constants)
    float4 ka[2], kb[2], qa[2], qb[2];
    float f0v[2], f1v[2], i0v[2], i1v[2], v0v[2], v1v[2], dv[2];

#pragma unroll
    for (int p = 0; p < 2; p++) {
        size_t o = (size_t)p * DD;
        ka[p] = *(const float4*)(pk + o); kb[p] = *(const float4*)(pk + o + 4);
        qa[p] = *(const float4*)(pq + o); qb[p] = *(const float4*)(pq + o + 4);
        f0v[p] = pf[o]; f1v[p] = pf[o + 1];
        i0v[p] = pi[o]; i1v[p] = pi[o + 1];
        v0v[p] = pv[o]; v1v[p] = pv[o + 1];
        dv[p] = pd[p];
    }

    for (int t0 = 0; t0 < SS; t0 += 16) {
#pragma unroll
        for (int u = 0; u < 16; u++) {
            const int s = u & 1;          // compile-time after unroll
            const int t = t0 + u;

            const float4 K0 = ka[s], K1 = kb[s];
            const float4 Q0 = qa[s], Q1 = qb[s];
            const float f0 = f0v[s], f1 = f1v[s];
            const float a0 = i0v[s] * v0v[s];
            const float a1 = i1v[s] * v1v[s];
            const float dinv = dv[s];

            // prefetch t+2 into this slot (arrays padded; no guard)
            {
                const size_t o = (size_t)(t + 2) * DD;
                ka[s] = *(const float4*)(pk + o); kb[s] = *(const float4*)(pk + o + 4);
                qa[s] = *(const float4*)(pq + o); qb[s] = *(const float4*)(pq + o + 4);
                f0v[s] = pf[o]; f1v[s] = pf[o + 1];
                i0v[s] = pi[o]; i1v[s] = pi[o + 1];
                v0v[s] = pv[o]; v1v[s] = pv[o + 1];
                dv[s] = pd[t + 2];
            }

            gg0 *= f0; gg1 *= f1;
            const float u0 = __fdividef(a0, gg0);
            const float u1 = __fdividef(a1, gg1);

            C0[0] = fmaf(u0, K0.x, C0[0]); C0[1] = fmaf(u0, K0.y, C0[1]);
            C0[2] = fmaf(u0, K0.z, C0[2]); C0[3] = fmaf(u0, K0.w, C0[3]);
            C0[4] = fmaf(u0, K1.x, C0[4]); C0[5] = fmaf(u0, K1.y, C0[5]);
            C0[6] = fmaf(u0, K1.z, C0[6]); C0[7] = fmaf(u0, K1.w, C0[7]);

            C1[0] = fmaf(u1, K0.x, C1[0]); C1[1] = fmaf(u1, K0.y, C1[1]);
            C1[2] = fmaf(u1, K0.z, C1[2]); C1[3] = fmaf(u1, K0.w, C1[3]);
            C1[4] = fmaf(u1, K1.x, C1[4]); C1[5] = fmaf(u1, K1.y, C1[5]);
            C1[6] = fmaf(u1, K1.z, C1[6]); C1[7] = fmaf(u1, K1.w, C1[7]);

            float d00 = C0[0] * Q0.x, d01 = C0[1] * Q0.y;
            float d02 = C0[2] * Q0.z, d03 = C0[3] * Q0.w;
            d00 = fmaf(C0[4], Q1.x, d00); d01 = fmaf(C0[5], Q1.y, d01);
            d02 = fmaf(C0[6], Q1.z, d02); d03 = fmaf(C0[7], Q1.w, d03);
            float n0 = (d00 + d01) + (d02 + d03);

            float d10 = C1[0] * Q0.x, d11 = C1[1] * Q0.y;
            float d12 = C1[2] * Q0.z, d13 = C1[3] * Q0.w;
            d10 = fmaf(C1[4], Q1.x, d10); d11 = fmaf(C1[5], Q1.y, d11);
            d12 = fmaf(C1[6], Q1.z, d12); d13 = fmaf(C1[7], Q1.w, d13);
            float n1 = (d10 + d11) + (d12 + d13);

#pragma unroll
            for (int o2 = 16; o2; o2 >>= 1) {
                n0 += __shfl_xor_sync(0xffffffffu, n0, o2);
                n1 += __shfl_xor_sync(0xffffffffu, n1, o2);
            }

            if (lane == 0) {
                ph[(size_t)t * DD]     = n0 * gg0 * dinv;
                ph[(size_t)t * DD + 1] = n1 * gg1 * dinv;
            }
        }
        // renormalize: fold chunk gate product back into state
#pragma unroll
        for (int c = 0; c < 8; c++) { C0[c] *= gg0; C1[c] *= gg1; }
        gg0 = 1.0f; gg1 = 1.0f;
    }
}

// ---------------------------------------------------------------------------
// Launch
// ---------------------------------------------------------------------------
extern "C" void kernel_launch(void* const* d_in, const int* in_sizes, int n_in,
                              void* d_out, int out_size)
{
    const float* x   = (const float*)d_in[0];
    const float* Wq  = (const float*)d_in[1];
    const float* bq  = (const float*)d_in[2];
    const float* Wk  = (const float*)d_in[3];
    const float* bkk = (const float*)d_in[4];
    // d_in[5] = Wv, d_in[6] = bv — unused (reference uses W_q for v)
    const float* Wf  = (const float*)d_in[7];
    const float* bff = (const float*)d_in[8];
    const float* Wi  = (const float*)d_in[9];
    const float* bii = (const float*)d_in[10];
    const float* Wo  = (const float*)d_in[11];
    const float* bo  = (const float*)d_in[12];
    float* out = (float*)d_out;

    float *pq, *pk, *pf, *pi, *ph;
    cudaGetSymbolAddress((void**)&pq, g_q);
    cudaGetSymbolAddress((void**)&pk, g_k);
    cudaGetSymbolAddress((void**)&pf, g_f);
    cudaGetSymbolAddress((void**)&pi, g_i);
    cudaGetSymbolAddress((void**)&ph, g_h);

    dim3 ggrid(DD / 64, MTOT / 64);   // (4, 128)

    gemm_kernel<0><<<ggrid, 256>>>(x, Wq, bq, pq);
    gemm_kernel<0><<<ggrid, 256>>>(x, Wk, bkk, pk);
    gemm_kernel<1><<<ggrid, 256>>>(x, Wf, bff, pf);
    gemm_kernel<2><<<ggrid, 256>>>(x, Wi, bii, pi);

    nscan_kernel<<<16, 128>>>();
    den_kernel<<<MTOT / 8, 256>>>();
    cscan_kernel<<<128, 256>>>();

    gemm_kernel<0><<<ggrid, 256>>>(ph, Wo, bo, out);
}

// round 3
// speedup vs baseline: 1.9975x; 1.0052x over previous
#include <cuda_runtime.h>
#include <math.h>

// Problem dims
constexpr int BB = 8;
constexpr int SS = 1024;
constexpr int DD = 256;
constexpr int MTOT = BB * SS;          // 8192
constexpr int PAD = 4 * DD;            // prefetch overrun pad

// Scratch (device globals — no cudaMalloc allowed)
__device__ float g_q[MTOT * DD + PAD];
__device__ float g_k[MTOT * DD + PAD];
__device__ float g_f[MTOT * DD + PAD];
__device__ float g_i[MTOT * DD + PAD];
__device__ float g_n[MTOT * DD];
__device__ float g_h[MTOT * DD];
__device__ float g_inv[MTOT + 16];

// ---- f32x2 helpers (packed fp32 pair ops; exact fp32 semantics) ----
__device__ __forceinline__ unsigned long long pack2(float lo, float hi) {
    unsigned long long r;
    asm("mov.b64 %0, {%1, %2};" : "=l"(r) : "f"(lo), "f"(hi));
    return r;
}
__device__ __forceinline__ unsigned long long fma2(
    unsigned long long a, unsigned long long b, unsigned long long c) {
    unsigned long long d;
    asm("fma.rn.f32x2 %0, %1, %2, %3;" : "=l"(d) : "l"(a), "l"(b), "l"(c));
    return d;
}
__device__ __forceinline__ void unpack2(unsigned long long v, float& lo, float& hi) {
    asm("mov.b64 {%0, %1}, %2;" : "=f"(lo), "=f"(hi) : "l"(v));
}

// ---------------------------------------------------------------------------
// GEMM: out[m,n] = act( sum_k A[m,k] * W[n,k] + bias[n] )
// A: [8192,256] rm, W: [256,256] rm. 64x64x16 tile, 4x4/thread, f32x2 FMA.
// ACT: 0 none, 1 sigmoid, 2 exp
// ---------------------------------------------------------------------------
template <int ACT>
__global__ void __launch_bounds__(256) gemm_kernel(
    const float* __restrict__ A, const float* __restrict__ W,
    const float* __restrict__ bias, float* __restrict__ out)
{
    constexpr int K = DD, N = DD;
    __shared__ float As[16][68];
    __shared__ float Bs[16][68];

    const int tid = threadIdx.x;
    const int m0 = blockIdx.y * 64;
    const int n0 = blockIdx.x * 64;
    const int lm = tid >> 2;
    const int lk = (tid & 3) << 2;
    const int tx = tid & 15;
    const int ty = tid >> 4;

    // acc2[i][jp]: rows i=0..3 (m), column pairs jp=0 -> (n,n+1), jp=1 -> (n+2,n+3)
    unsigned long long acc2[4][2] = {};

    for (int k0 = 0; k0 < K; k0 += 16) {
        float4 a4 = *(const float4*)(A + (size_t)(m0 + lm) * K + k0 + lk);
        float4 w4 = *(const float4*)(W + (size_t)(n0 + lm) * K + k0 + lk);
        As[lk + 0][lm] = a4.x; As[lk + 1][lm] = a4.y;
        As[lk + 2][lm] = a4.z; As[lk + 3][lm] = a4.w;
        Bs[lk + 0][lm] = w4.x; Bs[lk + 1][lm] = w4.y;
        Bs[lk + 2][lm] = w4.z; Bs[lk + 3][lm] = w4.w;
        __syncthreads();
#pragma unroll
        for (int kk = 0; kk < 16; kk++) {
            float4 av = *(const float4*)&As[kk][ty * 4];
            float4 bv = *(const float4*)&Bs[kk][tx * 4];
            // broadcast packs of a_i; b pairs
            unsigned long long b01 = pack2(bv.x, bv.y);
            unsigned long long b23 = pack2(bv.z, bv.w);
            float ar[4] = {av.x, av.y, av.z, av.w};
#pragma unroll
            for (int i2 = 0; i2 < 4; i2++) {
                unsigned long long aa = pack2(ar[i2], ar[i2]);
                acc2[i2][0] = fma2(aa, b01, acc2[i2][0]);
                acc2[i2][1] = fma2(aa, b23, acc2[i2][1]);
            }
        }
        __syncthreads();
    }

    float4 b4 = *(const float4*)(bias + n0 + tx * 4);
    float bb[4] = {b4.x, b4.y, b4.z, b4.w};
#pragma unroll
    for (int i2 = 0; i2 < 4; i2++) {
        float acc[4];
        unpack2(acc2[i2][0], acc[0], acc[1]);
        unpack2(acc2[i2][1], acc[2], acc[3]);
        float4 o;
        float* op = &o.x;
#pragma unroll
        for (int j2 = 0; j2 < 4; j2++) {
            float v = acc[j2] + bb[j2];
            if (ACT == 1) v = 1.0f / (1.0f + expf(-v));
            else if (ACT == 2) v = expf(v);
            op[j2] = v;
        }
        *(float4*)(out + (size_t)(m0 + ty * 4 + i2) * N + n0 + tx * 4) = o;
    }
}

// ---------------------------------------------------------------------------
// n-scan: n_t[j] = f_t[j]*n_{t-1}[j] + i_t[j]*k_t[j]
// ---------------------------------------------------------------------------
__global__ void nscan_kernel()
{
    const int b = blockIdx.x >> 1;
    const int j = ((blockIdx.x & 1) << 7) + threadIdx.x;
    const size_t base = (size_t)b * SS * DD + j;
    float n = 0.0f;
#pragma unroll 8
    for (int t = 0; t < SS; t++) {
        size_t o = base + (size_t)t * DD;
        n = fmaf(g_f[o], n, g_i[o] * g_k[o]);
        g_n[o] = n;
    }
}

// ---------------------------------------------------------------------------
// den: inv_den[b,t] = 1 / max(|n_t . q_t|, 1).  One warp per (b,t).
// ---------------------------------------------------------------------------
__global__ void den_kernel()
{
    const int warp = threadIdx.x >> 5;
    const int lane = threadIdx.x & 31;
    const int m = blockIdx.x * 8 + warp;
    const size_t base = (size_t)m * DD + lane * 8;
    float4 na = *(const float4*)(g_n + base);
    float4 nb = *(const float4*)(g_n + base + 4);
    float4 qa = *(const float4*)(g_q + base);
    float4 qb = *(const float4*)(g_q + base + 4);
    float d = na.x * qa.x + na.y * qa.y + na.z * qa.z + na.w * qa.w
            + nb.x * qb.x + nb.y * qb.y + nb.z * qb.z + nb.w * qb.w;
#pragma unroll
    for (int o = 16; o; o >>= 1) d += __shfl_xor_sync(0xffffffffu, d, o);
    if (lane == 0) g_inv[m] = 1.0f / fmaxf(fabsf(d), 1.0f);
}

// ---------------------------------------------------------------------------
// C-scan, rescaled form. One warp per 2 rows; lane owns columns
// {4*lane..4*lane+3} and {128+4*lane..128+4*lane+3}  -> all vector LDG.128
// are warp-contiguous (4 full 128B lines = 4 L1 wavefronts each).
//   g_t[r]   = prod of f within 16-step chunk (renormalized each chunk)
//   C~      += (i_t v_t / g_t) k_t
//   num_t    = g_t * (C~ . q_t);  h = num * inv_den   (v == q per reference)
// grid = 8 batches * 32 row-groups = 256 CTAs, 128 threads (4 warps, 8 rows).
// ---------------------------------------------------------------------------
__global__ void __launch_bounds__(128, 1) cscan_kernel()
{
    const int b = blockIdx.x >> 5;
    const int grp = blockIdx.x & 31;
    const int warp = threadIdx.x >> 5;
    const int lane = threadIdx.x & 31;
    const int row0 = grp * 8 + warp * 2;     // and row0+1
    const size_t mb = (size_t)b * SS * DD;

    const float* pk0 = g_k + mb + lane * 4;
    const float* pq0 = g_q + mb + lane * 4;
    const float* pf = g_f + mb + row0;       // float2 (row0, row0+1)
    const float* pi = g_i + mb + row0;
    const float* pv = g_q + mb + row0;       // v == q
    const float* pd = g_inv + b * SS;
    float* ph = g_h + mb + row0;

    float C0[8] = {0,0,0,0,0,0,0,0};
    float C1[8] = {0,0,0,0,0,0,0,0};
    float gg0 = 1.0f, gg1 = 1.0f;

    // double-buffer slots (compile-time indexed only)
    float4 ka[2], kb[2], qa[2], qb[2];
    float2 fv[2], iv[2], vv[2];
    float dv[2];

#pragma unroll
    for (int p = 0; p < 2; p++) {
        size_t o = (size_t)p * DD;
        ka[p] = *(const float4*)(pk0 + o);
        kb[p] = *(const float4*)(pk0 + o + 128);
        qa[p] = *(const float4*)(pq0 + o);
        qb[p] = *(const float4*)(pq0 + o + 128);
        fv[p] = *(const float2*)(pf + o);
        iv[p] = *(const float2*)(pi + o);
        vv[p] = *(const float2*)(pv + o);
        dv[p] = pd[p];
    }

    for (int t0 = 0; t0 < SS; t0 += 16) {
#pragma unroll
        for (int u = 0; u < 16; u++) {
            const int s = u & 1;              // compile-time after unroll
            const int t = t0 + u;

            const float4 K0 = ka[s], K1 = kb[s];
            const float4 Q0 = qa[s], Q1 = qb[s];
            const float2 F = fv[s], I = iv[s], V = vv[s];
            const float dinv = dv[s];

            // prefetch t+2 into this slot (arrays padded; no guard)
            {
                const size_t o = (size_t)(t + 2) * DD;
                ka[s] = *(const float4*)(pk0 + o);
                kb[s] = *(const float4*)(pk0 + o + 128);
                qa[s] = *(const float4*)(pq0 + o);
                qb[s] = *(const float4*)(pq0 + o + 128);
                fv[s] = *(const float2*)(pf + o);
                iv[s] = *(const float2*)(pi + o);
                vv[s] = *(const float2*)(pv + o);
                dv[s] = pd[t + 2];
            }

            gg0 *= F.x; gg1 *= F.y;
            const float u0 = __fdividef(I.x * V.x, gg0);
            const float u1 = __fdividef(I.y * V.y, gg1);

            C0[0] = fmaf(u0, K0.x, C0[0]); C0[1] = fmaf(u0, K0.y, C0[1]);
            C0[2] = fmaf(u0, K0.z, C0[2]); C0[3] = fmaf(u0, K0.w, C0[3]);
            C0[4] = fmaf(u0, K1.x, C0[4]); C0[5] = fmaf(u0, K1.y, C0[5]);
            C0[6] = fmaf(u0, K1.z, C0[6]); C0[7] = fmaf(u0, K1.w, C0[7]);

            C1[0] = fmaf(u1, K0.x, C1[0]); C1[1] = fmaf(u1, K0.y, C1[1]);
            C1[2] = fmaf(u1, K0.z, C1[2]); C1[3] = fmaf(u1, K0.w, C1[3]);
            C1[4] = fmaf(u1, K1.x, C1[4]); C1[5] = fmaf(u1, K1.y, C1[5]);
            C1[6] = fmaf(u1, K1.z, C1[6]); C1[7] = fmaf(u1, K1.w, C1[7]);

            float d00 = C0[0] * Q0.x, d01 = C0[1] * Q0.y;
            float d02 = C0[2] * Q0.z, d03 = C0[3] * Q0.w;
            d00 = fmaf(C0[4], Q1.x, d00); d01 = fmaf(C0[5], Q1.y, d01);
            d02 = fmaf(C0[6], Q1.z, d02); d03 = fmaf(C0[7], Q1.w, d03);
            float n0 = (d00 + d01) + (d02 + d03);

            float d10 = C1[0] * Q0.x, d11 = C1[1] * Q0.y;
            float d12 = C1[2] * Q0.z, d13 = C1[3] * Q0.w;
            d10 = fmaf(C1[4], Q1.x, d10); d11 = fmaf(C1[5], Q1.y, d11);
            d12 = fmaf(C1[6], Q1.z, d12); d13 = fmaf(C1[7], Q1.w, d13);
            float n1 = (d10 + d11) + (d12 + d13);

#pragma unroll
            for (int o2 = 16; o2; o2 >>= 1) {
                n0 += __shfl_xor_sync(0xffffffffu, n0, o2);
                n1 += __shfl_xor_sync(0xffffffffu, n1, o2);
            }

            if (lane == 0) {
                ph[(size_t)t * DD]     = n0 * gg0 * dinv;
                ph[(size_t)t * DD + 1] = n1 * gg1 * dinv;
            }
        }
        // fold chunk gate product back into state
#pragma unroll
        for (int c = 0; c < 8; c++) { C0[c] *= gg0; C1[c] *= gg1; }
        gg0 = 1.0f; gg1 = 1.0f;
    }
}

// ---------------------------------------------------------------------------
// Launch
// ---------------------------------------------------------------------------
extern "C" void kernel_launch(void* const* d_in, const int* in_sizes, int n_in,
                              void* d_out, int out_size)
{
    const float* x   = (const float*)d_in[0];
    const float* Wq  = (const float*)d_in[1];
    const float* bq  = (const float*)d_in[2];
    const float* Wk  = (const float*)d_in[3];
    const float* bkk = (const float*)d_in[4];
    // d_in[5] = Wv, d_in[6] = bv — unused (reference uses W_q for v)
    const float* Wf  = (const float*)d_in[7];
    const float* bff = (const float*)d_in[8];
    const float* Wi  = (const float*)d_in[9];
    const float* bii = (const float*)d_in[10];
    const float* Wo  = (const float*)d_in[11];
    const float* bo  = (const float*)d_in[12];
    float* out = (float*)d_out;

    float *pq, *pk, *pf, *pi, *ph;
    cudaGetSymbolAddress((void**)&pq, g_q);
    cudaGetSymbolAddress((void**)&pk, g_k);
    cudaGetSymbolAddress((void**)&pf, g_f);
    cudaGetSymbolAddress((void**)&pi, g_i);
    cudaGetSymbolAddress((void**)&ph, g_h);

    dim3 ggrid(DD / 64, MTOT / 64);   // (4, 128)

    gemm_kernel<0><<<ggrid, 256>>>(x, Wq, bq, pq);
    gemm_kernel<0><<<ggrid, 256>>>(x, Wk, bkk, pk);
    gemm_kernel<1><<<ggrid, 256>>>(x, Wf, bff, pf);
    gemm_kernel<2><<<ggrid, 256>>>(x, Wi, bii, pi);

    nscan_kernel<<<16, 128>>>();
    den_kernel<<<MTOT / 8, 256>>>();
    cscan_kernel<<<256, 128>>>();

    gemm_kernel<0><<<ggrid, 256>>>(ph, Wo, bo, out);
}

// round 4
// speedup vs baseline: 2.2324x; 1.1176x over previous
#include <cuda_runtime.h>
#include <math.h>
#include <stdint.h>

// Problem dims
constexpr int BB = 8;
constexpr int SS = 1024;
constexpr int DD = 256;
constexpr int MTOT = BB * SS;          // 8192
constexpr int PAD = 32 * DD;           // prefetch overrun pad

// Scratch (device globals — no cudaMalloc allowed)
__device__ float g_q[MTOT * DD + PAD];
__device__ float g_k[MTOT * DD + PAD];
__device__ float g_f[MTOT * DD + PAD];
__device__ float g_i[MTOT * DD + PAD];
__device__ float g_n[MTOT * DD];
__device__ float g_h[MTOT * DD];
__device__ float g_inv[MTOT + 64];

// ---- f32x2 helpers (packed fp32 pair ops; exact fp32 semantics) ----
__device__ __forceinline__ unsigned long long pack2(float lo, float hi) {
    unsigned long long r;
    asm("mov.b64 %0, {%1, %2};" : "=l"(r) : "f"(lo), "f"(hi));
    return r;
}
__device__ __forceinline__ unsigned long long fma2(
    unsigned long long a, unsigned long long b, unsigned long long c) {
    unsigned long long d;
    asm("fma.rn.f32x2 %0, %1, %2, %3;" : "=l"(d) : "l"(a), "l"(b), "l"(c));
    return d;
}
__device__ __forceinline__ unsigned long long mul2(
    unsigned long long a, unsigned long long b) {
    unsigned long long d;
    asm("mul.rn.f32x2 %0, %1, %2;" : "=l"(d) : "l"(a), "l"(b));
    return d;
}
__device__ __forceinline__ unsigned long long add2(
    unsigned long long a, unsigned long long b) {
    unsigned long long d;
    asm("add.rn.f32x2 %0, %1, %2;" : "=l"(d) : "l"(a), "l"(b));
    return d;
}
__device__ __forceinline__ void unpack2(unsigned long long v, float& lo, float& hi) {
    asm("mov.b64 {%0, %1}, %2;" : "=f"(lo), "=f"(hi) : "l"(v));
}

// ---- cp.async helpers ----
__device__ __forceinline__ void cp_async16(uint32_t saddr, const void* gptr) {
    asm volatile("cp.async.ca.shared.global [%0], [%1], 16;" :: "r"(saddr), "l"(gptr));
}
__device__ __forceinline__ void cp_async4(uint32_t saddr, const void* gptr) {
    asm volatile("cp.async.ca.shared.global [%0], [%1], 4;" :: "r"(saddr), "l"(gptr));
}
__device__ __forceinline__ void cp_commit() {
    asm volatile("cp.async.commit_group;");
}
template <int N>
__device__ __forceinline__ void cp_wait() {
    asm volatile("cp.async.wait_group %0;" :: "n"(N));
}

// ---------------------------------------------------------------------------
// GEMM: out[m,n] = act( sum_k A[m,k]*W[n,k] + bias[n] ).
// 128x128 tile, BK=8, 256 threads, 8x8 per thread, f32x2 FMA.
// 1 B smem traffic per FLOP (2x better than 64x64/4x4). ACT: 0/1/2.
// ---------------------------------------------------------------------------
template <int ACT>
__global__ void __launch_bounds__(256) gemm_kernel(
    const float* __restrict__ A, const float* __restrict__ W,
    const float* __restrict__ bias, float* __restrict__ out)
{
    __shared__ float As[8][132];
    __shared__ float Bs[8][132];

    const int tid = threadIdx.x;
    const int m0 = blockIdx.y * 128;
    const int n0 = blockIdx.x * 128;
    const int lm = tid >> 1;            // 0..127
    const int lk = (tid & 1) << 2;      // 0 or 4
    const int tx = tid & 15;            // n sub-tile
    const int ty = tid >> 4;            // m sub-tile

    unsigned long long acc2[8][4] = {};

    float4 a4 = *(const float4*)(A + (size_t)(m0 + lm) * DD + lk);
    float4 w4 = *(const float4*)(W + (size_t)(n0 + lm) * DD + lk);

    for (int k0 = 0; k0 < DD; k0 += 8) {
        __syncthreads();
        As[lk + 0][lm] = a4.x; As[lk + 1][lm] = a4.y;
        As[lk + 2][lm] = a4.z; As[lk + 3][lm] = a4.w;
        Bs[lk + 0][lm] = w4.x; Bs[lk + 1][lm] = w4.y;
        Bs[lk + 2][lm] = w4.z; Bs[lk + 3][lm] = w4.w;
        __syncthreads();
        if (k0 + 8 < DD) {      // prefetch next tile under compute
            a4 = *(const float4*)(A + (size_t)(m0 + lm) * DD + k0 + 8 + lk);
            w4 = *(const float4*)(W + (size_t)(n0 + lm) * DD + k0 + 8 + lk);
        }
#pragma unroll
        for (int kk = 0; kk < 8; kk++) {
            float4 av0 = *(const float4*)&As[kk][ty * 8];
            float4 av1 = *(const float4*)&As[kk][ty * 8 + 4];
            float4 bv0 = *(const float4*)&Bs[kk][tx * 8];
            float4 bv1 = *(const float4*)&Bs[kk][tx * 8 + 4];
            unsigned long long b0 = pack2(bv0.x, bv0.y);
            unsigned long long b1 = pack2(bv0.z, bv0.w);
            unsigned long long b2 = pack2(bv1.x, bv1.y);
            unsigned long long b3 = pack2(bv1.z, bv1.w);
            float am[8] = {av0.x, av0.y, av0.z, av0.w, av1.x, av1.y, av1.z, av1.w};
#pragma unroll
            for (int i2 = 0; i2 < 8; i2++) {
                unsigned long long aa = pack2(am[i2], am[i2]);
                acc2[i2][0] = fma2(aa, b0, acc2[i2][0]);
                acc2[i2][1] = fma2(aa, b1, acc2[i2][1]);
                acc2[i2][2] = fma2(aa, b2, acc2[i2][2]);
                acc2[i2][3] = fma2(aa, b3, acc2[i2][3]);
            }
        }
    }

    float4 bb0 = *(const float4*)(bias + n0 + tx * 8);
    float4 bb1 = *(const float4*)(bias + n0 + tx * 8 + 4);
    float bb[8] = {bb0.x, bb0.y, bb0.z, bb0.w, bb1.x, bb1.y, bb1.z, bb1.w};
#pragma unroll
    for (int i2 = 0; i2 < 8; i2++) {
        float r[8];
        unpack2(acc2[i2][0], r[0], r[1]);
        unpack2(acc2[i2][1], r[2], r[3]);
        unpack2(acc2[i2][2], r[4], r[5]);
        unpack2(acc2[i2][3], r[6], r[7]);
        float4 o0, o1;
        float* op = &o0.x;
#pragma unroll
        for (int j2 = 0; j2 < 8; j2++) {
            float v = r[j2] + bb[j2];
            if (ACT == 1) v = 1.0f / (1.0f + expf(-v));
            else if (ACT == 2) v = expf(v);
            if (j2 < 4) op[j2] = v; else (&o1.x)[j2 - 4] = v;
        }
        float* dst = out + (size_t)(m0 + ty * 8 + i2) * DD + n0 + tx * 8;
        *(float4*)dst = o0;
        *(float4*)(dst + 4) = o1;
    }
}

// ---------------------------------------------------------------------------
// n-scan: n_t[j] = f_t[j]*n_{t-1}[j] + i_t[j]*k_t[j]
// ---------------------------------------------------------------------------
__global__ void nscan_kernel()
{
    const int b = blockIdx.x >> 1;
    const int j = ((blockIdx.x & 1) << 7) + threadIdx.x;
    const size_t base = (size_t)b * SS * DD + j;
    float n = 0.0f;
#pragma unroll 8
    for (int t = 0; t < SS; t++) {
        size_t o = base + (size_t)t * DD;
        n = fmaf(g_f[o], n, g_i[o] * g_k[o]);
        g_n[o] = n;
    }
}

// ---------------------------------------------------------------------------
// den: inv_den[b,t] = 1 / max(|n_t . q_t|, 1).  One warp per (b,t).
// ---------------------------------------------------------------------------
__global__ void den_kernel()
{
    const int warp = threadIdx.x >> 5;
    const int lane = threadIdx.x & 31;
    const int m = blockIdx.x * 8 + warp;
    const size_t base = (size_t)m * DD + lane * 8;
    float4 na = *(const float4*)(g_n + base);
    float4 nb = *(const float4*)(g_n + base + 4);
    float4 qa = *(const float4*)(g_q + base);
    float4 qb = *(const float4*)(g_q + base + 4);
    float d = na.x * qa.x + na.y * qa.y + na.z * qa.z + na.w * qa.w
            + nb.x * qb.x + nb.y * qb.y + nb.z * qb.z + nb.w * qb.w;
#pragma unroll
    for (int o = 16; o; o >>= 1) d += __shfl_xor_sync(0xffffffffu, d, o);
    if (lane == 0) g_inv[m] = 1.0f / fmaxf(fabsf(d), 1.0f);
}

// ---------------------------------------------------------------------------
// C-scan, cp.async SMEM-pipelined, rescaled form, f32x2 math.
// CTA = 128 threads (4 warps), owns 16 rows of one batch (grid 8*16=128).
// Warp owns 4 rows; lane owns cols {4L..4L+3, 128+4L..128+4L+3}.
// k_t/q_t staged ONCE per CTA in SMEM (shared by all warps) via a
// 2-stage x 8-timestep cp.async ring (8-step lookahead covers L2 latency).
//   gg_r  = running f-product within 16-step window (renorm every 16)
//   C~   += (i v / gg) k   ;  num = gg * (C~ . q) ;  h = num * inv_den
// ---------------------------------------------------------------------------
constexpr int TS  = 8;     // timesteps per stage
constexpr int NST = 2;     // stages

__global__ void __launch_bounds__(128, 1) cscan_kernel()
{
    __shared__ float sk[NST][TS][DD];      // 16 KB
    __shared__ float sq[NST][TS][DD];      // 16 KB
    __shared__ float sg[NST][TS][48];      // f[16] i[16] v[16] per t
    __shared__ float sd[NST][TS];          // inv_den

    const int b    = blockIdx.x >> 4;
    const int grp  = blockIdx.x & 15;
    const int tid  = threadIdx.x;
    const int warp = tid >> 5;
    const int lane = tid & 31;
    const size_t mb = (size_t)b * SS * DD;
    const int rowb = grp * 16;             // CTA's 16 rows

    const uint32_t sk_u = (uint32_t)__cvta_generic_to_shared(&sk[0][0][0]);
    const uint32_t sq_u = (uint32_t)__cvta_generic_to_shared(&sq[0][0][0]);
    const uint32_t sg_u = (uint32_t)__cvta_generic_to_shared(&sg[0][0][0]);
    const uint32_t sd_u = (uint32_t)__cvta_generic_to_shared(&sd[0][0]);

    // stage filler: issues cp.asyncs for timesteps [tt, tt+8)
    auto fill = [&](int st, int tt) {
#pragma unroll
        for (int j = 0; j < 4; j++) {               // k: 512 16B-granules
            int idx = tid + j * 128;
            int t = idx >> 6, gr = idx & 63;
            cp_async16(sk_u + (uint32_t)(((st * TS + t) * DD + gr * 4) * 4),
                       g_k + mb + (size_t)(tt + t) * DD + gr * 4);
        }
#pragma unroll
        for (int j = 0; j < 4; j++) {               // q: 512 granules
            int idx = tid + j * 128;
            int t = idx >> 6, gr = idx & 63;
            cp_async16(sq_u + (uint32_t)(((st * TS + t) * DD + gr * 4) * 4),
                       g_q + mb + (size_t)(tt + t) * DD + gr * 4);
        }
        {                                            // gates: f,i,v rows [rowb..rowb+15]
            int t = tid >> 4, gi = tid & 15;
            if (gi < 12) {
                int gate = gi >> 2, part = gi & 3;
                const float* src =
                    (gate == 0 ? g_f : (gate == 1 ? g_i : g_q))   // v == q
                    + mb + (size_t)(tt + t) * DD + rowb + part * 4;
                cp_async16(sg_u + (uint32_t)(((st * TS + t) * 48 + gate * 16 + part * 4) * 4),
                           src);
            }
        }
        if (tid < TS)
            cp_async4(sd_u + (uint32_t)((st * TS + tid) * 4),
                      g_inv + b * SS + tt + tid);
    };

    // per-warp state
    float* ph = g_h + mb + rowb + warp * 4;          // 4-row output base
    unsigned long long C2[4][4];                     // 4 rows x 8 cols (pairs)
#pragma unroll
    for (int r = 0; r < 4; r++)
#pragma unroll
        for (int c = 0; c < 4; c++) C2[r][c] = 0ull;
    float gg[4] = {1.0f, 1.0f, 1.0f, 1.0f};

    // prologue
    fill(0, 0); cp_commit();
    fill(1, TS); cp_commit();

    for (int blk = 0; blk < SS / TS; blk++) {
        const int st = blk & 1;
        cp_wait<1>();
        __syncthreads();

#pragma unroll
        for (int u = 0; u < TS; u++) {
            const int t = blk * TS + u;
            const float4* k4 = (const float4*)&sk[st][u][0];
            const float4* q4 = (const float4*)&sq[st][u][0];
            float4 K0 = k4[lane], K1 = k4[32 + lane];
            float4 Q0 = q4[lane], Q1 = q4[32 + lane];
            float4 F = *(const float4*)&sg[st][u][warp * 4];
            float4 I = *(const float4*)&sg[st][u][16 + warp * 4];
            float4 V = *(const float4*)&sg[st][u][32 + warp * 4];
            const float dinv = sd[st][u];

            gg[0] *= F.x; gg[1] *= F.y; gg[2] *= F.z; gg[3] *= F.w;
            float uu[4];
            uu[0] = __fdividef(I.x * V.x, gg[0]);
            uu[1] = __fdividef(I.y * V.y, gg[1]);
            uu[2] = __fdividef(I.z * V.z, gg[2]);
            uu[3] = __fdividef(I.w * V.w, gg[3]);

            unsigned long long k2[4] = {pack2(K0.x, K0.y), pack2(K0.z, K0.w),
                                        pack2(K1.x, K1.y), pack2(K1.z, K1.w)};
            unsigned long long q2[4] = {pack2(Q0.x, Q0.y), pack2(Q0.z, Q0.w),
                                        pack2(Q1.x, Q1.y), pack2(Q1.z, Q1.w)};

            float nres[4];
#pragma unroll
            for (int r = 0; r < 4; r++) {
                unsigned long long u2 = pack2(uu[r], uu[r]);
                C2[r][0] = fma2(u2, k2[0], C2[r][0]);
                C2[r][1] = fma2(u2, k2[1], C2[r][1]);
                C2[r][2] = fma2(u2, k2[2], C2[r][2]);
                C2[r][3] = fma2(u2, k2[3], C2[r][3]);
                unsigned long long d0 = mul2(C2[r][0], q2[0]);
                unsigned long long d1 = mul2(C2[r][1], q2[1]);
                d0 = fma2(C2[r][2], q2[2], d0);
                d1 = fma2(C2[r][3], q2[3], d1);
                unsigned long long s = add2(d0, d1);
                float lo, hi; unpack2(s, lo, hi);
                nres[r] = lo + hi;
            }
#pragma unroll
            for (int o2 = 16; o2; o2 >>= 1) {
                nres[0] += __shfl_xor_sync(0xffffffffu, nres[0], o2);
                nres[1] += __shfl_xor_sync(0xffffffffu, nres[1], o2);
                nres[2] += __shfl_xor_sync(0xffffffffu, nres[2], o2);
                nres[3] += __shfl_xor_sync(0xffffffffu, nres[3], o2);
            }
            if (lane == 0) {
                float4 o = make_float4(nres[0] * gg[0] * dinv,
                                       nres[1] * gg[1] * dinv,
                                       nres[2] * gg[2] * dinv,
                                       nres[3] * gg[3] * dinv);
                *(float4*)(ph + (size_t)t * DD) = o;
            }
        }

        // renormalize every 16 steps (2 blocks)
        if (blk & 1) {
#pragma unroll
            for (int r = 0; r < 4; r++) {
                unsigned long long g2 = pack2(gg[r], gg[r]);
                C2[r][0] = mul2(C2[r][0], g2);
                C2[r][1] = mul2(C2[r][1], g2);
                C2[r][2] = mul2(C2[r][2], g2);
                C2[r][3] = mul2(C2[r][3], g2);
                gg[r] = 1.0f;
            }
        }

        __syncthreads();
        const int nb = blk + NST;
        if (nb < SS / TS) fill(st, nb * TS);
        cp_commit();
    }
}

// ---------------------------------------------------------------------------
// Launch
// ---------------------------------------------------------------------------
extern "C" void kernel_launch(void* const* d_in, const int* in_sizes, int n_in,
                              void* d_out, int out_size)
{
    const float* x   = (const float*)d_in[0];
    const float* Wq  = (const float*)d_in[1];
    const float* bq  = (const float*)d_in[2];
    const float* Wk  = (const float*)d_in[3];
    const float* bkk = (const float*)d_in[4];
    // d_in[5] = Wv, d_in[6] = bv — unused (reference uses W_q for v)
    const float* Wf  = (const float*)d_in[7];
    const float* bff = (const float*)d_in[8];
    const float* Wi  = (const float*)d_in[9];
    const float* bii = (const float*)d_in[10];
    const float* Wo  = (const float*)d_in[11];
    const float* bo  = (const float*)d_in[12];
    float* out = (float*)d_out;

    float *pq, *pk, *pf, *pi, *ph;
    cudaGetSymbolAddress((void**)&pq, g_q);
    cudaGetSymbolAddress((void**)&pk, g_k);
    cudaGetSymbolAddress((void**)&pf, g_f);
    cudaGetSymbolAddress((void**)&pi, g_i);
    cudaGetSymbolAddress((void**)&ph, g_h);

    dim3 ggrid(DD / 128, MTOT / 128);   // (2, 64) = 128 CTAs

    gemm_kernel<0><<<ggrid, 256>>>(x, Wq, bq, pq);
    gemm_kernel<0><<<ggrid, 256>>>(x, Wk, bkk, pk);
    gemm_kernel<1><<<ggrid, 256>>>(x, Wf, bff, pf);
    gemm_kernel<2><<<ggrid, 256>>>(x, Wi, bii, pi);

    nscan_kernel<<<16, 128>>>();
    den_kernel<<<MTOT / 8, 256>>>();
    cscan_kernel<<<BB * 16, 128>>>();

    gemm_kernel<0><<<ggrid, 256>>>(ph, Wo, bo, out);
}